// round 6
// baseline (speedup 1.0000x reference)
#include <cuda_runtime.h>

// SceneEngine: closed-form subset-sum factorization.
//   Σ over non-empty subsets of exp(Σ_s exist[s,bit_s]) = Π_s(e0+e1) − Π_s e0
//   number_prob  -> elementary symmetric polynomial DP on Π_s(e0 + t·e1)
//   attr prob[d] -> (Π_s(e0 + e1·exp(a[s,d])) − Π_s e0) / Z
//
// R5 (re-bench; prior run was an infra failure): block = 128 threads = 32
// pairs. Coalesced in AND out:
//   1) stage inputs GMEM->SMEM via float4 (coalesced)
//   2) 4 role warps compute from SMEM, write results to an SMEM out-buffer
//      shaped as the block's slice of each output segment
//   3) flush out-buffer -> GMEM via coalesced float4 stores
// Rules (6 scalars/block) written directly.

constexpr int NS = 9;

constexpr int OFF_EXIST  = 0;
constexpr int OFF_NUM    = 73728;
constexpr int OFF_TYPE   = 110592;
constexpr int OFF_NTYPE  = 135168;
constexpr int OFF_RTYPE  = 145408;
constexpr int OFF_SIZE   = 145664;
constexpr int OFF_NSIZE  = 174336;
constexpr int OFF_RSIZE  = 186624;
constexpr int OFF_COLOR  = 186880;
constexpr int OFF_NCOLOR = 231936;
constexpr int OFF_RCOLOR = 252416;

// input staging (floats per block of 32 pairs)
constexpr int SEG_EX = 576, SEG_TY = 1440, SEG_SI = 1728, SEG_CO = 2880;
constexpr int IN_EX = 0;
constexpr int IN_TY = IN_EX + SEG_EX;
constexpr int IN_SI = IN_TY + SEG_TY;
constexpr int IN_CO = IN_SI + SEG_SI;
constexpr int IN_TOT = IN_CO + SEG_CO;          // 6624

// output staging (floats per block): mirrors global per-block slices
constexpr int L_EX  = 0;      // [32][18]
constexpr int L_NUM = 576;    // [32][9]
constexpr int L_TY  = 864;    // [32][6]
constexpr int L_NTY = 1056;   // [2][8][5]
constexpr int L_SI  = 1136;   // [32][7]
constexpr int L_NSI = 1360;   // [2][8][6]
constexpr int L_CO  = 1456;   // [32][11]
constexpr int L_NCO = 1808;   // [2][8][10]
constexpr int L_TOT = 1968;

#define BIGF 3.402823466e+38f

__device__ __forceinline__ void copy4(float* __restrict__ dst,
                                      const float* __restrict__ src,
                                      int n4, int t)
{
    float4* __restrict__ d = (float4*)dst;
    const float4* __restrict__ s = (const float4*)src;
    for (int i = t; i < n4; i += 128) d[i] = s[i];
}

__device__ __forceinline__ float min8(float v)
{
#pragma unroll
    for (int off = 4; off >= 1; off >>= 1)
        v = fminf(v, __shfl_xor_sync(0xFFFFFFFFu, v, off));
    return v;
}

__device__ __forceinline__ void load_exist(const float* __restrict__ s_ex,
                                           int lane, float e0[NS], float e1[NS])
{
    const float* r = s_ex + lane * 18;
#pragma unroll
    for (int s = 0; s < NS; s++) {
        e0[s] = __expf(r[2 * s + 0]);
        e1[s] = __expf(r[2 * s + 1]);
    }
}

template <int D>
__device__ __forceinline__ void attr_role(
    const float* __restrict__ s_attr,   // SMEM input segment [32][9][D]
    float* __restrict__ s_out,          // SMEM output buffer
    const float* __restrict__ s_ex,
    int lane, int b, int k,
    float* __restrict__ out,
    int l_prob, int l_norm, int off_rule)
{
    float e0[NS], e1[NS];
    load_exist(s_ex, lane, e0, e1);

    float S0 = 1.0f, Zp = 1.0f;
#pragma unroll
    for (int s = 0; s < NS; s++) { S0 *= e0[s]; Zp *= (e0[s] + e1[s]); }
    float invZ = __fdividef(1.0f, Zp - S0);

    const float* __restrict__ a = s_attr + lane * NS * D;
    float p[D];
#pragma unroll
    for (int d = 0; d < D; d++) p[d] = 1.0f;
#pragma unroll
    for (int s = 0; s < NS; s++) {
#pragma unroll
        for (int d = 0; d < D; d++)
            p[d] *= fmaf(e1[s], __expf(a[s * D + d]), e0[s]);
    }

    float sum = 0.0f;
#pragma unroll
    for (int d = 0; d < D; d++) {
        p[d] = (p[d] - S0) * invZ;
        sum += p[d];
    }
    float nic = fminf(sum, 1.0f);

    float* __restrict__ op = s_out + l_prob + lane * (D + 1);
#pragma unroll
    for (int d = 0; d < D; d++) op[d] = p[d];
    op[D] = 1.0f - nic;

    if (k < 8) {
        float inv = __fdividef(1.0f, sum);
        // local b index = lane>>4 (0 or 1)
        float* __restrict__ on = s_out + l_norm + ((lane >> 4) * 8 + k) * D;
#pragma unroll
        for (int d = 0; d < D; d++) on[d] = p[d] * inv;
    }

    float v = (k < 8) ? nic : BIGF;
    v = min8(v);
    if (k == 0) out[off_rule + b] = v;   // lanes 0 & 16 (two different b)
}

__global__ __launch_bounds__(128)
void scene_engine_kernel(const float* __restrict__ exist,
                         const float* __restrict__ typ,
                         const float* __restrict__ siz,
                         const float* __restrict__ col,
                         float* __restrict__ out)
{
    __shared__ __align__(16) float s_in[IN_TOT];
    __shared__ __align__(16) float s_out[L_TOT];

    int t = threadIdx.x;
    int blk = blockIdx.x;

    // ---- coalesced input staging ----
    copy4(s_in + IN_EX, exist + (size_t)blk * SEG_EX, SEG_EX / 4, t);
    copy4(s_in + IN_TY, typ   + (size_t)blk * SEG_TY, SEG_TY / 4, t);
    copy4(s_in + IN_SI, siz   + (size_t)blk * SEG_SI, SEG_SI / 4, t);
    copy4(s_in + IN_CO, col   + (size_t)blk * SEG_CO, SEG_CO / 4, t);
    __syncthreads();

    int w = t >> 5;
    int lane = t & 31;
    int pair = blk * 32 + lane;
    int b = pair >> 4;
    int k = lane & 15;

    if (w == 0) {
        float e0[NS], e1[NS];
        load_exist(s_in + IN_EX, lane, e0, e1);

        float* __restrict__ oex = s_out + L_EX + lane * 18;
#pragma unroll
        for (int s = 0; s < NS; s++) {
            ((float2*)oex)[s] = make_float2(e0[s], e1[s]);
        }

        // elementary symmetric polynomial DP
        float c[NS + 1];
        c[0] = 1.0f;
#pragma unroll
        for (int i = 1; i <= NS; i++) c[i] = 0.0f;
#pragma unroll
        for (int s = 0; s < NS; s++) {
#pragma unroll
            for (int j = NS; j >= 1; j--)
                c[j] = fmaf(c[j], e0[s], c[j - 1] * e1[s]);
            c[0] *= e0[s];
        }
        float Z = 0.0f;
#pragma unroll
        for (int j = 1; j <= NS; j++) Z += c[j];
        float invZ = __fdividef(1.0f, Z);

        float* __restrict__ onum = s_out + L_NUM + lane * NS;
#pragma unroll
        for (int n = 0; n < NS; n++) onum[n] = c[n + 1] * invZ;
    } else if (w == 1) {
        attr_role<5>(s_in + IN_TY, s_out, s_in + IN_EX, lane, b, k, out,
                     L_TY, L_NTY, OFF_RTYPE);
    } else if (w == 2) {
        attr_role<6>(s_in + IN_SI, s_out, s_in + IN_EX, lane, b, k, out,
                     L_SI, L_NSI, OFF_RSIZE);
    } else {
        attr_role<10>(s_in + IN_CO, s_out, s_in + IN_EX, lane, b, k, out,
                      L_CO, L_NCO, OFF_RCOLOR);
    }
    __syncthreads();

    // ---- coalesced output flush ----
    copy4(out + OFF_EXIST  + (size_t)blk * 576, s_out + L_EX,  144, t);
    copy4(out + OFF_NUM    + (size_t)blk * 288, s_out + L_NUM,  72, t);
    copy4(out + OFF_TYPE   + (size_t)blk * 192, s_out + L_TY,   48, t);
    copy4(out + OFF_NTYPE  + (size_t)blk *  80, s_out + L_NTY,  20, t);
    copy4(out + OFF_SIZE   + (size_t)blk * 224, s_out + L_SI,   56, t);
    copy4(out + OFF_NSIZE  + (size_t)blk *  96, s_out + L_NSI,  24, t);
    copy4(out + OFF_COLOR  + (size_t)blk * 352, s_out + L_CO,   88, t);
    copy4(out + OFF_NCOLOR + (size_t)blk * 160, s_out + L_NCO,  40, t);
}

extern "C" void kernel_launch(void* const* d_in, const int* in_sizes, int n_in,
                              void* d_out, int out_size)
{
    const float* exist = (const float*)d_in[0];
    const float* typ   = (const float*)d_in[1];
    const float* siz   = (const float*)d_in[2];
    const float* col   = (const float*)d_in[3];
    float* out = (float*)d_out;

    // 128 blocks × 128 threads; 32 pairs per block.
    scene_engine_kernel<<<128, 128>>>(exist, typ, siz, col, out);
}

// round 7
// speedup vs baseline: 1.2308x; 1.2308x over previous
#include <cuda_runtime.h>

// SceneEngine: closed-form subset-sum factorization.
//   Σ over non-empty subsets of exp(Σ_s exist[s,bit_s]) = Π_s(e0+e1) − Π_s e0
//   number_prob  -> elementary symmetric polynomial DP on Π_s(e0 + t·e1)
//   attr prob[d] -> (Π_s(e0 + e1·exp(a[s,d])) − Π_s e0) / Z
//
// R7: barrier-free role warps (R2 structure), rebalanced so the slowest
// warp's serial chain shrinks 117 -> 72 exps.
//   block = 160 threads = 5 warps = 32 pairs:
//     w0: exist_prob + symmetric DP + number      (18 exps/lane)
//     w1: type D=5, lane=pair                     (63 exps/lane)
//     w2: size D=6, lane=pair                     (72 exps/lane)
//     w3: color d-halves, pairs 0-15  (lane=(p<<1)|h, 63 exps/lane)
//     w4: color d-halves, pairs 16-31
// Cross-half combine via one shfl_xor(1); no __syncthreads anywhere.

constexpr int NS = 9;

constexpr int OFF_EXIST  = 0;
constexpr int OFF_NUM    = 73728;
constexpr int OFF_TYPE   = 110592;
constexpr int OFF_NTYPE  = 135168;
constexpr int OFF_RTYPE  = 145408;
constexpr int OFF_SIZE   = 145664;
constexpr int OFF_NSIZE  = 174336;
constexpr int OFF_RSIZE  = 186624;
constexpr int OFF_COLOR  = 186880;
constexpr int OFF_NCOLOR = 231936;
constexpr int OFF_RCOLOR = 252416;

#define BIGF 3.402823466e+38f

__device__ __forceinline__ void load_exist_g(const float* __restrict__ exist,
                                             int pair, float e0[NS], float e1[NS])
{
    const float* __restrict__ r = exist + (size_t)pair * 18;
#pragma unroll
    for (int s = 0; s < NS; s++) {
        e0[s] = __expf(r[2 * s + 0]);
        e1[s] = __expf(r[2 * s + 1]);
    }
}

// min across 8-lane subgroup (for warps where lane = pair, k = lane&15)
__device__ __forceinline__ float min8(float v)
{
#pragma unroll
    for (int off = 4; off >= 1; off >>= 1)
        v = fminf(v, __shfl_xor_sync(0xFFFFFFFFu, v, off));
    return v;
}

// full-warp attribute role: lane = local pair (32 pairs), attr dim D
template <int D>
__device__ __forceinline__ void attr_full(
    const float* __restrict__ attr,
    const float* __restrict__ exist,
    int pair, int b, int k,
    float* __restrict__ out,
    int off_prob, int off_norm, int off_rule)
{
    float e0[NS], e1[NS];
    load_exist_g(exist, pair, e0, e1);

    float S0 = 1.0f, Zp = 1.0f;
#pragma unroll
    for (int s = 0; s < NS; s++) { S0 *= e0[s]; Zp *= (e0[s] + e1[s]); }
    float invZ = __fdividef(1.0f, Zp - S0);

    const float* __restrict__ a = attr + (size_t)pair * NS * D;
    float p[D];
#pragma unroll
    for (int d = 0; d < D; d++) p[d] = 1.0f;
#pragma unroll
    for (int s = 0; s < NS; s++) {
#pragma unroll
        for (int d = 0; d < D; d++)
            p[d] *= fmaf(e1[s], __expf(a[s * D + d]), e0[s]);
    }

    float sum = 0.0f;
#pragma unroll
    for (int d = 0; d < D; d++) {
        p[d] = (p[d] - S0) * invZ;
        sum += p[d];
    }
    float nic = fminf(sum, 1.0f);

    float* __restrict__ op = out + off_prob + (size_t)pair * (D + 1);
#pragma unroll
    for (int d = 0; d < D; d++) op[d] = p[d];
    op[D] = 1.0f - nic;

    if (k < 8) {
        float inv = __fdividef(1.0f, sum);
        float* __restrict__ on = out + off_norm + (size_t)(b * 8 + k) * D;
#pragma unroll
        for (int d = 0; d < D; d++) on[d] = p[d] * inv;
    }

    float v = (k < 8) ? nic : BIGF;
    v = min8(v);
    if (k == 0) out[off_rule + b] = v;   // lanes 0 & 16 (two b's)
}

// color role, d-split: warp covers 16 pairs (one b); lane = (p_loc<<1)|half,
// each lane handles 5 of the 10 color dims.
__device__ __forceinline__ void color_half(
    const float* __restrict__ col,
    const float* __restrict__ exist,
    int pair_base,                       // global pair index of this warp's pair 0
    int lane,
    float* __restrict__ out)
{
    int k    = lane >> 1;                // 0..15 (= local pair = k)
    int h    = lane & 1;
    int pair = pair_base + k;
    int b    = pair >> 4;

    float e0[NS], e1[NS];
    load_exist_g(exist, pair, e0, e1);

    float S0 = 1.0f, Zp = 1.0f;
#pragma unroll
    for (int s = 0; s < NS; s++) { S0 *= e0[s]; Zp *= (e0[s] + e1[s]); }
    float invZ = __fdividef(1.0f, Zp - S0);

    const float* __restrict__ a = col + (size_t)pair * 90 + h * 5;
    float p[5];
#pragma unroll
    for (int d = 0; d < 5; d++) p[d] = 1.0f;
#pragma unroll
    for (int s = 0; s < NS; s++) {
#pragma unroll
        for (int d = 0; d < 5; d++)
            p[d] *= fmaf(e1[s], __expf(a[s * 10 + d]), e0[s]);
    }

    float part = 0.0f;
#pragma unroll
    for (int d = 0; d < 5; d++) {
        p[d] = (p[d] - S0) * invZ;
        part += p[d];
    }
    float sum = part + __shfl_xor_sync(0xFFFFFFFFu, part, 1);
    float nic = fminf(sum, 1.0f);

    float* __restrict__ op = out + OFF_COLOR + (size_t)pair * 11 + h * 5;
#pragma unroll
    for (int d = 0; d < 5; d++) op[d] = p[d];
    if (h) op[5] = 1.0f - nic;           // element 10

    if (k < 8) {
        float inv = __fdividef(1.0f, sum);
        float* __restrict__ on = out + OFF_NCOLOR + (size_t)(b * 8 + k) * 10 + h * 5;
#pragma unroll
        for (int d = 0; d < 5; d++) on[d] = p[d] * inv;
    }

    float v = (k < 8) ? nic : BIGF;
#pragma unroll
    for (int off = 16; off >= 1; off >>= 1)
        v = fminf(v, __shfl_xor_sync(0xFFFFFFFFu, v, off));
    if (lane == 0) out[OFF_RCOLOR + b] = v;
}

__global__ __launch_bounds__(160)
void scene_engine_kernel(const float* __restrict__ exist,
                         const float* __restrict__ typ,
                         const float* __restrict__ siz,
                         const float* __restrict__ col,
                         float* __restrict__ out)
{
    int t = threadIdx.x;
    int w = t >> 5;
    int lane = t & 31;
    int blk = blockIdx.x;
    int pair = blk * 32 + lane;          // for w0..w2 (lane = local pair)
    int b = pair >> 4;
    int k = lane & 15;

    if (w == 0) {
        float e0[NS], e1[NS];
        load_exist_g(exist, pair, e0, e1);

        float* __restrict__ oex = out + OFF_EXIST + (size_t)pair * 18;
#pragma unroll
        for (int s = 0; s < NS; s++) {
            oex[2 * s + 0] = e0[s];
            oex[2 * s + 1] = e1[s];
        }

        // elementary symmetric polynomial DP
        float c[NS + 1];
        c[0] = 1.0f;
#pragma unroll
        for (int i = 1; i <= NS; i++) c[i] = 0.0f;
#pragma unroll
        for (int s = 0; s < NS; s++) {
#pragma unroll
            for (int j = NS; j >= 1; j--)
                c[j] = fmaf(c[j], e0[s], c[j - 1] * e1[s]);
            c[0] *= e0[s];
        }
        float Z = 0.0f;
#pragma unroll
        for (int j = 1; j <= NS; j++) Z += c[j];
        float invZ = __fdividef(1.0f, Z);

        float* __restrict__ onum = out + OFF_NUM + (size_t)pair * NS;
#pragma unroll
        for (int n = 0; n < NS; n++) onum[n] = c[n + 1] * invZ;
    } else if (w == 1) {
        attr_full<5>(typ, exist, pair, b, k, out, OFF_TYPE, OFF_NTYPE, OFF_RTYPE);
    } else if (w == 2) {
        attr_full<6>(siz, exist, pair, b, k, out, OFF_SIZE, OFF_NSIZE, OFF_RSIZE);
    } else if (w == 3) {
        color_half(col, exist, blk * 32, lane, out);
    } else {
        color_half(col, exist, blk * 32 + 16, lane, out);
    }
}

extern "C" void kernel_launch(void* const* d_in, const int* in_sizes, int n_in,
                              void* d_out, int out_size)
{
    const float* exist = (const float*)d_in[0];
    const float* typ   = (const float*)d_in[1];
    const float* siz   = (const float*)d_in[2];
    const float* col   = (const float*)d_in[3];
    float* out = (float*)d_out;

    // 128 blocks × 160 threads (5 role warps per 32 pairs), single wave.
    scene_engine_kernel<<<128, 160>>>(exist, typ, siz, col, out);
}